// round 14
// baseline (speedup 1.0000x reference)
#include <cuda_runtime.h>
#include <math.h>

#define BB 2048
#define TT 2048
#define CC 8
#define AA 27
#define HH 8

__device__ __forceinline__ float tanh_approx(float v) {
    float r;
    asm("tanh.approx.f32 %0, %1;" : "=f"(r) : "f"(v));
    return r;
}

__device__ __forceinline__ float elu(float y) {
    return (y > 0.0f) ? y : expm1f(y);
}

// Fused, minimal-state. Grid 16384 (8 blocks/row), 256 threads, ONE t per
// thread (2 LDG.128 live across the barrier -> low regs, high occupancy,
// tiny blocks -> negligible wave tail). Per-row MLP runs once per block in
// warp 0 (warp-cooperative shfl) into smem; the other warps' prefetched x
// loads stay in flight across the single barrier.
__global__ void __launch_bounds__(256) fused_kernel(
    const float* __restrict__ x,
    const float* __restrict__ attrs,
    const float* __restrict__ w1,  const float* __restrict__ b1,
    const float* __restrict__ w2,  const float* __restrict__ b2,
    const float* __restrict__ bw1, const float* __restrict__ bb1,
    const float* __restrict__ bw2, const float* __restrict__ bb2,
    const float* __restrict__ mask_a,
    const float* __restrict__ mask_h,
    float* __restrict__ out)
{
    __shared__ float sk[CC];
    __shared__ float sbias;

    int tid  = threadIdx.x;
    int wid  = tid >> 5;
    int lane = tid & 31;
    int b    = blockIdx.x >> 3;                 // 8 blocks per row
    int t    = ((blockIdx.x & 7) << 8) + tid;   // this thread's timestep

    // ---- prefetch this thread's x (stays in flight across the barrier) ----
    const float4* xp = (const float4*)(x + ((unsigned)(b * TT + t)) * CC);
    float4 x0 = __ldcs(&xp[0]);
    float4 x1 = __ldcs(&xp[1]);

    // ---- warp 0: warp-cooperative MLP -> smem ----
    if (wid == 0) {
        const unsigned FULL = 0xFFFFFFFFu;
        int h = lane & 7;
        int g = lane >> 3;

        float hw = 0.0f, hb = 0.0f;
#pragma unroll
        for (int s = 0; s < 7; s++) {
            int i = g + 4 * s;
            if (i < AA) {
                float ai = attrs[b * AA + i] * mask_a[b * AA + i];
                hw = fmaf(ai, w1[i * HH + h], hw);
                hb = fmaf(ai, bw1[i * HH + h], hb);
            }
        }
        hw += __shfl_xor_sync(FULL, hw, 8);
        hw += __shfl_xor_sync(FULL, hw, 16);
        hb += __shfl_xor_sync(FULL, hb, 8);
        hb += __shfl_xor_sync(FULL, hb, 16);

        float m = mask_h[b * HH + h];
        hw = fmaxf(hw + b1[h], 0.0f) * m;
        hb = fmaxf(hb + bb1[h], 0.0f) * m;

        float kacc = b2[h];
        float bacc = bb2[0];
#pragma unroll
        for (int hh = 0; hh < 8; hh++) {
            float hwv = __shfl_sync(FULL, hw, hh);
            float hbv = __shfl_sync(FULL, hb, hh);
            kacc = fmaf(hwv, w2[hh * CC + h], kacc);
            bacc = fmaf(hbv, bw2[hh], bacc);
        }
        float kc = tanh_approx(kacc);
        if (lane < 8)  sk[lane] = kc;
        if (lane == 0) sbias = tanh_approx(bacc);
    }
    __syncthreads();

    // ---- contraction + ELU ----
    float y = sbias;
    y = fmaf(x0.x, sk[0], y); y = fmaf(x0.y, sk[1], y);
    y = fmaf(x0.z, sk[2], y); y = fmaf(x0.w, sk[3], y);
    y = fmaf(x1.x, sk[4], y); y = fmaf(x1.y, sk[5], y);
    y = fmaf(x1.z, sk[6], y); y = fmaf(x1.w, sk[7], y);

    __stcs(&out[(unsigned)(b * TT + t)], elu(y));
}

extern "C" void kernel_launch(void* const* d_in, const int* in_sizes, int n_in,
                              void* d_out, int out_size) {
    const float* x      = (const float*)d_in[0];
    const float* attrs  = (const float*)d_in[1];
    const float* w1     = (const float*)d_in[2];
    const float* b1     = (const float*)d_in[3];
    const float* w2     = (const float*)d_in[4];
    const float* b2     = (const float*)d_in[5];
    const float* bw1    = (const float*)d_in[6];
    const float* bb1    = (const float*)d_in[7];
    const float* bw2    = (const float*)d_in[8];
    const float* bb2    = (const float*)d_in[9];
    const float* mask_a = (const float*)d_in[10];
    const float* mask_h = (const float*)d_in[11];
    float* out = (float*)d_out;

    fused_kernel<<<BB * 8, 256>>>(x, attrs, w1, b1, w2, b2,
                                  bw1, bb1, bw2, bb2,
                                  mask_a, mask_h, out);
}

// round 15
// speedup vs baseline: 1.1402x; 1.1402x over previous
#include <cuda_runtime.h>
#include <math.h>

#define BB 2048
#define TT 2048
#define CC 8
#define AA 27
#define HH 8

__device__ __forceinline__ float tanh_approx(float v) {
    float r;
    asm("tanh.approx.f32 %0, %1;" : "=f"(r) : "f"(v));
    return r;
}

__device__ __forceinline__ float elu(float y) {
    return (y > 0.0f) ? y : expm1f(y);
}

// R10 shape (best measured kernel: no barrier, no smem, per-warp shfl MLP,
// one block per row, 8 t/thread, pair-ahead pipeline) with occupancy forced
// to 7 blocks/SM via launch_bounds (regs 40 -> 36, occ 65% -> ~87%).
__global__ void __launch_bounds__(256, 7) fused_kernel(
    const float* __restrict__ x,
    const float* __restrict__ attrs,
    const float* __restrict__ w1,  const float* __restrict__ b1,
    const float* __restrict__ w2,  const float* __restrict__ b2,
    const float* __restrict__ bw1, const float* __restrict__ bb1,
    const float* __restrict__ bw2, const float* __restrict__ bb2,
    const float* __restrict__ mask_a,
    const float* __restrict__ mask_h,
    float* __restrict__ out)
{
    int b   = blockIdx.x;
    int tid = threadIdx.x;

    const float4* xrow = (const float4*)(x + (long)b * TT * CC);

    // ---- prefetch first two t's before the MLP (independent work) ----
    float4 p0a = __ldcs(&xrow[tid * 2]);
    float4 p0b = __ldcs(&xrow[tid * 2 + 1]);
    float4 p1a = __ldcs(&xrow[(tid + 256) * 2]);
    float4 p1b = __ldcs(&xrow[(tid + 256) * 2 + 1]);

    // ---- warp-cooperative MLP (no smem, no __syncthreads) ----
    const unsigned FULL = 0xFFFFFFFFu;
    int lane = tid & 31;
    int h = lane & 7;        // hidden unit handled by this lane
    int g = lane >> 3;       // i-group (0..3)

    float hw = 0.0f, hb = 0.0f;
#pragma unroll
    for (int s = 0; s < 7; s++) {
        int i = g + 4 * s;
        if (i < AA) {
            float ai = attrs[b * AA + i] * mask_a[b * AA + i];
            hw = fmaf(ai, w1[i * HH + h], hw);
            hb = fmaf(ai, bw1[i * HH + h], hb);
        }
    }
    hw += __shfl_xor_sync(FULL, hw, 8);
    hw += __shfl_xor_sync(FULL, hw, 16);
    hb += __shfl_xor_sync(FULL, hb, 8);
    hb += __shfl_xor_sync(FULL, hb, 16);

    float m = mask_h[b * HH + h];
    hw = fmaxf(hw + b1[h], 0.0f) * m;
    hb = fmaxf(hb + bb1[h], 0.0f) * m;

    float kacc = b2[h];
    float bacc = bb2[0];
#pragma unroll
    for (int hh = 0; hh < 8; hh++) {
        float hwv = __shfl_sync(FULL, hw, hh);
        float hbv = __shfl_sync(FULL, hb, hh);
        kacc = fmaf(hwv, w2[hh * CC + h], kacc);
        bacc = fmaf(hbv, bw2[hh], bacc);
    }
    float kc   = tanh_approx(kacc);
    float bias = tanh_approx(bacc);          // lane-uniform

    float k0 = __shfl_sync(FULL, kc, 0);
    float k1 = __shfl_sync(FULL, kc, 1);
    float k2 = __shfl_sync(FULL, kc, 2);
    float k3 = __shfl_sync(FULL, kc, 3);
    float k4 = __shfl_sync(FULL, kc, 4);
    float k5 = __shfl_sync(FULL, kc, 5);
    float k6 = __shfl_sync(FULL, kc, 6);
    float k7 = __shfl_sync(FULL, kc, 7);

    float* orow = out + (long)b * TT;

    // ---- pipelined contraction: compute pair j while loading pair j+2 ----
#pragma unroll
    for (int j = 0; j < 8; j += 2) {
        float4 n0a, n0b, n1a, n1b;
        if (j + 2 < 8) {
            int u0 = tid + 256 * (j + 2);
            int u1 = tid + 256 * (j + 3);
            n0a = __ldcs(&xrow[u0 * 2]); n0b = __ldcs(&xrow[u0 * 2 + 1]);
            n1a = __ldcs(&xrow[u1 * 2]); n1b = __ldcs(&xrow[u1 * 2 + 1]);
        }

        float ya = bias;
        ya = fmaf(p0a.x, k0, ya); ya = fmaf(p0a.y, k1, ya);
        ya = fmaf(p0a.z, k2, ya); ya = fmaf(p0a.w, k3, ya);
        ya = fmaf(p0b.x, k4, ya); ya = fmaf(p0b.y, k5, ya);
        ya = fmaf(p0b.z, k6, ya); ya = fmaf(p0b.w, k7, ya);

        float yb = bias;
        yb = fmaf(p1a.x, k0, yb); yb = fmaf(p1a.y, k1, yb);
        yb = fmaf(p1a.z, k2, yb); yb = fmaf(p1a.w, k3, yb);
        yb = fmaf(p1b.x, k4, yb); yb = fmaf(p1b.y, k5, yb);
        yb = fmaf(p1b.z, k6, yb); yb = fmaf(p1b.w, k7, yb);

        __stcs(&orow[tid + 256 * j],       elu(ya));
        __stcs(&orow[tid + 256 * (j + 1)], elu(yb));

        p0a = n0a; p0b = n0b;
        p1a = n1a; p1b = n1b;
    }
}

extern "C" void kernel_launch(void* const* d_in, const int* in_sizes, int n_in,
                              void* d_out, int out_size) {
    const float* x      = (const float*)d_in[0];
    const float* attrs  = (const float*)d_in[1];
    const float* w1     = (const float*)d_in[2];
    const float* b1     = (const float*)d_in[3];
    const float* w2     = (const float*)d_in[4];
    const float* b2     = (const float*)d_in[5];
    const float* bw1    = (const float*)d_in[6];
    const float* bb1    = (const float*)d_in[7];
    const float* bw2    = (const float*)d_in[8];
    const float* bb2    = (const float*)d_in[9];
    const float* mask_a = (const float*)d_in[10];
    const float* mask_h = (const float*)d_in[11];
    float* out = (float*)d_out;

    fused_kernel<<<BB, 256>>>(x, attrs, w1, b1, w2, b2,
                              bw1, bb1, bw2, bb2,
                              mask_a, mask_h, out);
}